// round 16
// baseline (speedup 1.0000x reference)
#include <cuda_runtime.h>
#include <cuda_bf16.h>
#include <math.h>
#include <float.h>

#define Nn   2000
#define Aa   16
#define OBSd 64
#define Hh   128
#define Ee   16000
#define NITER 8
#define IN_DIM 80
#define G3    384
#define E2    (2*Ee)

/* ---------------- scratch (static device globals) ------------------------ */
__device__ __align__(16) float g_gi[Nn*G3];
__device__ __align__(16) float g_gh[Nn*G3];
__device__ __align__(16) float g_h[Nn*Hh];
__device__ __align__(16) float g_hA[Nn*Hh];
__device__ __align__(16) float g_hB[Nn*Hh];
__device__ __align__(16) float g_ua[Nn*256];
__device__ __align__(16) float g_ub[Nn*256];
__device__ __align__(16) float g_ual[Nn*Aa];            /* aligned copy of u */
__device__ __align__(16) float g_pal[(size_t)Ee*256];   /* aligned copy of p */
__device__ __align__(16) __nv_bfloat16 g_a0h[(size_t)E2*Hh];
__device__ __align__(16) __nv_bfloat16 g_a0l[(size_t)E2*Hh];
__device__ __align__(16) __nv_bfloat16 g_a1h[(size_t)E2*256];
__device__ __align__(16) __nv_bfloat16 g_a1l[(size_t)E2*256];
__device__ __align__(16) __nv_bfloat16 g_a2h[(size_t)E2*256];
__device__ __align__(16) __nv_bfloat16 g_a2l[(size_t)E2*256];
__device__ __align__(16) __nv_bfloat16 g_w1h[256*Hh],  g_w1l[256*Hh];
__device__ __align__(16) __nv_bfloat16 g_w2h[256*256], g_w2l[256*256];
__device__ __align__(16) float g_M[Ee*2*Aa];
__device__ __align__(16) float g_S[3*Nn*Aa];     /* triple-buffered */
__device__ int   g_map[Nn*Nn];
__device__ int   g_isrep[Ee];
__device__ int   g_aidx[2][Nn];
__device__ int   g_best[Nn];
__device__ float g_part[64];
__device__ int   g_qctr;
__device__ float g_qmax;

/* ---------------- bf16 split helper ---------------------------------------- */
__device__ __forceinline__ void split2(float v0, float v1, unsigned& h, unsigned& l) {
    __nv_bfloat162 hh = __floats2bfloat162_rn(v0, v1);
    float r0 = v0 - __bfloat162float(hh.x);
    float r1 = v1 - __bfloat162float(hh.y);
    __nv_bfloat162 ll = __floats2bfloat162_rn(r0, r1);
    h = *reinterpret_cast<unsigned*>(&hh);
    l = *reinterpret_cast<unsigned*>(&ll);
}

/* ---------------- cp.async helpers ------------------------------------------ */
__device__ __forceinline__ unsigned smem_u32(const void* p) {
    return (unsigned)__cvta_generic_to_shared(p);
}
#define CP16(dst, src) \
    asm volatile("cp.async.cg.shared.global [%0], [%1], 16;" :: "r"(dst), "l"(src))
#define CP_COMMIT() asm volatile("cp.async.commit_group;")
#define CP_WAIT(n)  asm volatile("cp.async.wait_group %0;" :: "n"(n))

/* ---------------- init ------------------------------------------------------ */
__global__ void k_init() {
    int idx = blockIdx.x*blockDim.x + threadIdx.x;
    int stride = gridDim.x*blockDim.x;
    for (int i = idx; i < Ee*2*Aa; i += stride) g_M[i]   = 0.f;
    for (int i = idx; i < 3*Nn*Aa; i += stride) g_S[i]   = 0.f;
    for (int i = idx; i < Nn; i += stride)      g_best[i] = -1;
    if (idx == 0) { g_qmax = 0.f; g_qctr = 0; }
}

__global__ void k_clearmap(const int* __restrict__ edges) {
    int e = blockIdx.x*blockDim.x + threadIdx.x;
    if (e >= Ee) return;
    g_map[edges[2*e]*Nn + edges[2*e+1]] = 0x7fffffff;
}

__global__ void k_mapbuild(const int* __restrict__ edges) {
    int e = blockIdx.x*blockDim.x + threadIdx.x;
    if (e >= Ee) return;
    atomicMin(&g_map[edges[2*e]*Nn + edges[2*e+1]], e);
}

__global__ void k_isrep(const int* __restrict__ edges) {
    int e = blockIdx.x*blockDim.x + threadIdx.x;
    if (e >= Ee) return;
    g_isrep[e] = (g_map[edges[2*e]*Nn + edges[2*e+1]] == e) ? 1 : 0;
}

/* ---------------- weight split --------------------------------------------- */
__global__ void k_wsplit(const float* __restrict__ W, int n,
                         __nv_bfloat16* __restrict__ Wh, __nv_bfloat16* __restrict__ Wl) {
    int i = blockIdx.x*blockDim.x + threadIdx.x;
    if (i >= n) return;
    float v = W[i];
    __nv_bfloat16 h = __float2bfloat16(v);
    Wh[i] = h;
    Wl[i] = __float2bfloat16(v - __bfloat162float(h));
}

/* ---------------- 128x128x8 double-buffered SGEMM (fp32) ------------------- */
#define BM 128
#define BN 128
#define BK 8

__global__ __launch_bounds__(256,2)
void k_gemm128(const float* __restrict__ X, int lda,
               const float* __restrict__ W, int ldw,
               const float* __restrict__ bias, float* __restrict__ C,
               int M, int N, int K, int relu, float scale, float bias_mult,
               int vec_store)
{
    __shared__ __align__(16) float As[2][BK][BM+4];
    __shared__ __align__(16) float Bs[2][BK][BN+4];
    const int t   = threadIdx.x;
    const int bm  = blockIdx.y * BM;
    const int bn  = blockIdx.x * BN;
    const int lrow = t >> 1;
    const int lcol = (t & 1) << 2;
    const int tx = t & 15, ty = t >> 4;
    const int cx0 = tx << 2, cx1 = 64 + (tx << 2);
    const int ry0 = ty << 2, ry1 = 64 + (ty << 2);

    float acc[8][8];
#pragma unroll
    for (int i = 0; i < 8; i++)
#pragma unroll
        for (int j = 0; j < 8; j++) acc[i][j] = 0.f;

    const bool xok = (bm + lrow) < M;
    const bool wok = (bn + lrow) < N;
    const float* Xp = X + (size_t)(bm + lrow)*lda + lcol;
    const float* Wp = W + (size_t)(bn + lrow)*ldw + lcol;
    const float4 z4 = make_float4(0.f,0.f,0.f,0.f);

    float4 xa = xok ? *reinterpret_cast<const float4*>(Xp) : z4;
    float4 wa = wok ? *reinterpret_cast<const float4*>(Wp) : z4;
    As[0][lcol+0][lrow]=xa.x; As[0][lcol+1][lrow]=xa.y; As[0][lcol+2][lrow]=xa.z; As[0][lcol+3][lrow]=xa.w;
    Bs[0][lcol+0][lrow]=wa.x; Bs[0][lcol+1][lrow]=wa.y; Bs[0][lcol+2][lrow]=wa.z; Bs[0][lcol+3][lrow]=wa.w;
    __syncthreads();

    int buf = 0;
    for (int k0 = 0; k0 < K; k0 += BK) {
        const bool more = (k0 + BK) < K;
        float4 xn = z4, wn = z4;
        if (more) {
            if (xok) xn = *reinterpret_cast<const float4*>(Xp + k0 + BK);
            if (wok) wn = *reinterpret_cast<const float4*>(Wp + k0 + BK);
        }
#pragma unroll
        for (int k = 0; k < BK; k++) {
            float4 a0 = *reinterpret_cast<const float4*>(&As[buf][k][ry0]);
            float4 a1 = *reinterpret_cast<const float4*>(&As[buf][k][ry1]);
            float4 b0 = *reinterpret_cast<const float4*>(&Bs[buf][k][cx0]);
            float4 b1 = *reinterpret_cast<const float4*>(&Bs[buf][k][cx1]);
            float ar[8] = {a0.x,a0.y,a0.z,a0.w,a1.x,a1.y,a1.z,a1.w};
            float br[8] = {b0.x,b0.y,b0.z,b0.w,b1.x,b1.y,b1.z,b1.w};
#pragma unroll
            for (int i = 0; i < 8; i++)
#pragma unroll
                for (int j = 0; j < 8; j++)
                    acc[i][j] = fmaf(ar[i], br[j], acc[i][j]);
        }
        if (more) {
            int nb = buf ^ 1;
            As[nb][lcol+0][lrow]=xn.x; As[nb][lcol+1][lrow]=xn.y; As[nb][lcol+2][lrow]=xn.z; As[nb][lcol+3][lrow]=xn.w;
            Bs[nb][lcol+0][lrow]=wn.x; Bs[nb][lcol+1][lrow]=wn.y; Bs[nb][lcol+2][lrow]=wn.z; Bs[nb][lcol+3][lrow]=wn.w;
            __syncthreads();
            buf = nb;
        }
    }

    float4 bv0 = *reinterpret_cast<const float4*>(&bias[bn + cx0]);
    float4 bv1 = *reinterpret_cast<const float4*>(&bias[bn + cx1]);
#pragma unroll
    for (int ii = 0; ii < 8; ii++) {
        int r = bm + ((ii < 4) ? (ry0 + ii) : (ry1 + ii - 4));
        if (r >= M) continue;
        float o[8];
        o[0]=acc[ii][0]+bias_mult*bv0.x; o[1]=acc[ii][1]+bias_mult*bv0.y;
        o[2]=acc[ii][2]+bias_mult*bv0.z; o[3]=acc[ii][3]+bias_mult*bv0.w;
        o[4]=acc[ii][4]+bias_mult*bv1.x; o[5]=acc[ii][5]+bias_mult*bv1.y;
        o[6]=acc[ii][6]+bias_mult*bv1.z; o[7]=acc[ii][7]+bias_mult*bv1.w;
        if (relu) {
#pragma unroll
            for (int j = 0; j < 8; j++) o[j] = fmaxf(o[j], 0.f);
        }
#pragma unroll
        for (int j = 0; j < 8; j++) o[j] *= scale;
        if (vec_store) {
            *reinterpret_cast<float4*>(&C[(size_t)r*N + bn + cx0]) = make_float4(o[0],o[1],o[2],o[3]);
            *reinterpret_cast<float4*>(&C[(size_t)r*N + bn + cx1]) = make_float4(o[4],o[5],o[6],o[7]);
        } else {
            float* c0 = &C[(size_t)r*N + bn + cx0];
            float* c1 = &C[(size_t)r*N + bn + cx1];
            c0[0]=o[0]; c0[1]=o[1]; c0[2]=o[2]; c0[3]=o[3];
            c1[0]=o[4]; c1[1]=o[5]; c1[2]=o[6]; c1[3]=o[7];
        }
    }
}

/* ---------------- gi GEMM with fused concat loader ------------------------- */
__device__ __forceinline__ float4 ld_concat(const float* __restrict__ x,
                                            const float* __restrict__ pa,
                                            int row, int c) {
    return (c < OBSd) ? *reinterpret_cast<const float4*>(x + (size_t)row*OBSd + c)
                      : *reinterpret_cast<const float4*>(pa + (size_t)row*Aa + (c - OBSd));
}

__global__ __launch_bounds__(256,2)
void k_gemmGI(const float* __restrict__ x, const float* __restrict__ pa,
              const float* __restrict__ W, int ldw,
              const float* __restrict__ bias, float* __restrict__ C,
              int M, int N, int K)
{
    __shared__ __align__(16) float As[2][BK][BM+4];
    __shared__ __align__(16) float Bs[2][BK][BN+4];
    const int t   = threadIdx.x;
    const int bm  = blockIdx.y * BM;
    const int bn  = blockIdx.x * BN;
    const int lrow = t >> 1;
    const int lcol = (t & 1) << 2;
    const int tx = t & 15, ty = t >> 4;
    const int cx0 = tx << 2, cx1 = 64 + (tx << 2);
    const int ry0 = ty << 2, ry1 = 64 + (ty << 2);

    float acc[8][8];
#pragma unroll
    for (int i = 0; i < 8; i++)
#pragma unroll
        for (int j = 0; j < 8; j++) acc[i][j] = 0.f;

    const bool xok = (bm + lrow) < M;
    const bool wok = (bn + lrow) < N;
    const int arow = bm + lrow;
    const float* Wp = W + (size_t)(bn + lrow)*ldw + lcol;
    const float4 z4 = make_float4(0.f,0.f,0.f,0.f);

    float4 xa = xok ? ld_concat(x, pa, arow, lcol) : z4;
    float4 wa = wok ? *reinterpret_cast<const float4*>(Wp) : z4;
    As[0][lcol+0][lrow]=xa.x; As[0][lcol+1][lrow]=xa.y; As[0][lcol+2][lrow]=xa.z; As[0][lcol+3][lrow]=xa.w;
    Bs[0][lcol+0][lrow]=wa.x; Bs[0][lcol+1][lrow]=wa.y; Bs[0][lcol+2][lrow]=wa.z; Bs[0][lcol+3][lrow]=wa.w;
    __syncthreads();

    int buf = 0;
    for (int k0 = 0; k0 < K; k0 += BK) {
        const bool more = (k0 + BK) < K;
        float4 xn = z4, wn = z4;
        if (more) {
            if (xok) xn = ld_concat(x, pa, arow, k0 + BK + lcol);
            if (wok) wn = *reinterpret_cast<const float4*>(Wp + k0 + BK);
        }
#pragma unroll
        for (int k = 0; k < BK; k++) {
            float4 a0 = *reinterpret_cast<const float4*>(&As[buf][k][ry0]);
            float4 a1 = *reinterpret_cast<const float4*>(&As[buf][k][ry1]);
            float4 b0 = *reinterpret_cast<const float4*>(&Bs[buf][k][cx0]);
            float4 b1 = *reinterpret_cast<const float4*>(&Bs[buf][k][cx1]);
            float ar[8] = {a0.x,a0.y,a0.z,a0.w,a1.x,a1.y,a1.z,a1.w};
            float br[8] = {b0.x,b0.y,b0.z,b0.w,b1.x,b1.y,b1.z,b1.w};
#pragma unroll
            for (int i = 0; i < 8; i++)
#pragma unroll
                for (int j = 0; j < 8; j++)
                    acc[i][j] = fmaf(ar[i], br[j], acc[i][j]);
        }
        if (more) {
            int nb = buf ^ 1;
            As[nb][lcol+0][lrow]=xn.x; As[nb][lcol+1][lrow]=xn.y; As[nb][lcol+2][lrow]=xn.z; As[nb][lcol+3][lrow]=xn.w;
            Bs[nb][lcol+0][lrow]=wn.x; Bs[nb][lcol+1][lrow]=wn.y; Bs[nb][lcol+2][lrow]=wn.z; Bs[nb][lcol+3][lrow]=wn.w;
            __syncthreads();
            buf = nb;
        }
    }

    float4 bv0 = *reinterpret_cast<const float4*>(&bias[bn + cx0]);
    float4 bv1 = *reinterpret_cast<const float4*>(&bias[bn + cx1]);
#pragma unroll
    for (int ii = 0; ii < 8; ii++) {
        int r = bm + ((ii < 4) ? (ry0 + ii) : (ry1 + ii - 4));
        if (r >= M) continue;
        float o[8];
        o[0]=acc[ii][0]+bv0.x; o[1]=acc[ii][1]+bv0.y;
        o[2]=acc[ii][2]+bv0.z; o[3]=acc[ii][3]+bv0.w;
        o[4]=acc[ii][4]+bv1.x; o[5]=acc[ii][5]+bv1.y;
        o[6]=acc[ii][6]+bv1.z; o[7]=acc[ii][7]+bv1.w;
        *reinterpret_cast<float4*>(&C[(size_t)r*N + bn + cx0]) = make_float4(o[0],o[1],o[2],o[3]);
        *reinterpret_cast<float4*>(&C[(size_t)r*N + bn + cx1]) = make_float4(o[4],o[5],o[6],o[7]);
    }
}

/* ---------------- split-bf16 tensor GEMM, cp.async double-buffered ---------- */
#define TBM 128
#define TBN 64
#define TBK 32

#define MMA_BF16(c, a, b) \
    asm volatile("mma.sync.aligned.m16n8k16.row.col.f32.bf16.bf16.f32 " \
        "{%0,%1,%2,%3}, {%4,%5,%6,%7}, {%8,%9}, {%0,%1,%2,%3};" \
        : "+f"((c)[0]), "+f"((c)[1]), "+f"((c)[2]), "+f"((c)[3]) \
        : "r"((a)[0]), "r"((a)[1]), "r"((a)[2]), "r"((a)[3]), "r"((b)[0]), "r"((b)[1]))

__device__ __forceinline__ unsigned lds_bf2(const __nv_bfloat16* p) {
    return *reinterpret_cast<const unsigned*>(p);
}

__global__ __launch_bounds__(256,2)
void k_tgemm(const __nv_bfloat16* __restrict__ Ah, const __nv_bfloat16* __restrict__ Al,
             const __nv_bfloat16* __restrict__ Bh, const __nv_bfloat16* __restrict__ Bl,
             const float* __restrict__ bias, int M, int N, int K,
             __nv_bfloat16* __restrict__ Ch, __nv_bfloat16* __restrict__ Cl)
{
    __shared__ __align__(16) __nv_bfloat16 sAh[2][TBM][TBK+8];
    __shared__ __align__(16) __nv_bfloat16 sAl[2][TBM][TBK+8];
    __shared__ __align__(16) __nv_bfloat16 sBh[2][TBN][TBK+8];
    __shared__ __align__(16) __nv_bfloat16 sBl[2][TBN][TBK+8];

    const int t = threadIdx.x;
    const int bm = blockIdx.y * TBM;
    const int bn = blockIdx.x * TBN;
    const int wid = t >> 5;
    const int lane = t & 31;
    const int g  = lane >> 2;
    const int tg = lane & 3;
    const int warp_m = (wid & 3) * 32;
    const int warp_n = (wid >> 2) * 32;

    float c[2][4][4];
#pragma unroll
    for (int mi = 0; mi < 2; mi++)
#pragma unroll
        for (int ni = 0; ni < 4; ni++)
#pragma unroll
            for (int q = 0; q < 4; q++) c[mi][ni][q] = 0.f;

    const int ar = t >> 1;
    const int ac = (t & 1) * 16;
    const int br = t >> 2;
    const int bc = (t & 3) * 8;

    const __nv_bfloat16* pAh = Ah + (size_t)(bm+ar)*K + ac;
    const __nv_bfloat16* pAl = Al + (size_t)(bm+ar)*K + ac;
    const __nv_bfloat16* pBh = Bh + (size_t)(bn+br)*K + bc;
    const __nv_bfloat16* pBl = Bl + (size_t)(bn+br)*K + bc;

#define LD_TILE(bb, kk) do { \
        CP16(smem_u32(&sAh[bb][ar][ac]),     pAh + (kk)); \
        CP16(smem_u32(&sAh[bb][ar][ac + 8]), pAh + (kk) + 8); \
        CP16(smem_u32(&sAl[bb][ar][ac]),     pAl + (kk)); \
        CP16(smem_u32(&sAl[bb][ar][ac + 8]), pAl + (kk) + 8); \
        CP16(smem_u32(&sBh[bb][br][bc]),     pBh + (kk)); \
        CP16(smem_u32(&sBl[bb][br][bc]),     pBl + (kk)); \
        CP_COMMIT(); \
    } while (0)

    LD_TILE(0, 0);
    int buf = 0;
    for (int kk = 0; kk < K; kk += TBK) {
        const bool more = (kk + TBK) < K;
        if (more) LD_TILE(buf ^ 1, kk + TBK);
        if (more) CP_WAIT(1); else CP_WAIT(0);
        __syncthreads();

#pragma unroll
        for (int k16 = 0; k16 < TBK; k16 += 16) {
            unsigned ah[2][4], al[2][4], bh[4][2], bl[4][2];
#pragma unroll
            for (int mi = 0; mi < 2; mi++) {
                int rb = warp_m + mi*16;
                ah[mi][0] = lds_bf2(&sAh[buf][rb+g  ][k16 + 2*tg]);
                ah[mi][1] = lds_bf2(&sAh[buf][rb+g+8][k16 + 2*tg]);
                ah[mi][2] = lds_bf2(&sAh[buf][rb+g  ][k16 + 2*tg + 8]);
                ah[mi][3] = lds_bf2(&sAh[buf][rb+g+8][k16 + 2*tg + 8]);
                al[mi][0] = lds_bf2(&sAl[buf][rb+g  ][k16 + 2*tg]);
                al[mi][1] = lds_bf2(&sAl[buf][rb+g+8][k16 + 2*tg]);
                al[mi][2] = lds_bf2(&sAl[buf][rb+g  ][k16 + 2*tg + 8]);
                al[mi][3] = lds_bf2(&sAl[buf][rb+g+8][k16 + 2*tg + 8]);
            }
#pragma unroll
            for (int ni = 0; ni < 4; ni++) {
                int cb = warp_n + ni*8;
                bh[ni][0] = lds_bf2(&sBh[buf][cb+g][k16 + 2*tg]);
                bh[ni][1] = lds_bf2(&sBh[buf][cb+g][k16 + 2*tg + 8]);
                bl[ni][0] = lds_bf2(&sBl[buf][cb+g][k16 + 2*tg]);
                bl[ni][1] = lds_bf2(&sBl[buf][cb+g][k16 + 2*tg + 8]);
            }
#pragma unroll
            for (int mi = 0; mi < 2; mi++)
#pragma unroll
                for (int ni = 0; ni < 4; ni++) {
                    MMA_BF16(c[mi][ni], ah[mi], bh[ni]);
                    MMA_BF16(c[mi][ni], ah[mi], bl[ni]);
                    MMA_BF16(c[mi][ni], al[mi], bh[ni]);
                }
        }
        __syncthreads();
        buf ^= 1;
    }
#undef LD_TILE

#pragma unroll
    for (int mi = 0; mi < 2; mi++) {
        int r0 = bm + warp_m + mi*16 + g;
        int r1 = r0 + 8;
#pragma unroll
        for (int ni = 0; ni < 4; ni++) {
            int cb = bn + warp_n + ni*8 + 2*tg;
            float b0 = bias[cb], b1 = bias[cb+1];
            float v0 = fmaxf(c[mi][ni][0] + b0, 0.f);
            float v1 = fmaxf(c[mi][ni][1] + b1, 0.f);
            float v2 = fmaxf(c[mi][ni][2] + b0, 0.f);
            float v3 = fmaxf(c[mi][ni][3] + b1, 0.f);
            unsigned h01, l01, h23, l23;
            split2(v0, v1, h01, l01);
            split2(v2, v3, h23, l23);
            *reinterpret_cast<unsigned*>(&Ch[(size_t)r0*N + cb]) = h01;
            *reinterpret_cast<unsigned*>(&Cl[(size_t)r0*N + cb]) = l01;
            *reinterpret_cast<unsigned*>(&Ch[(size_t)r1*N + cb]) = h23;
            *reinterpret_cast<unsigned*>(&Cl[(size_t)r1*N + cb]) = l23;
        }
    }
}

/* ---------------- skinny GEMM, N=16, dual-store (u + aligned copy) --------- */
__global__ __launch_bounds__(256,4)
void k_gemm16(const float* __restrict__ X, int lda,
              const float* __restrict__ W, int ldw,
              const float* __restrict__ bias, float* __restrict__ C,
              float* __restrict__ C2,
              int M, int K, int relu, float scale)
{
    __shared__ __align__(16) float As[16][BM+4];
    __shared__ float Bs[16][17];
    const int t = threadIdx.x;
    const int bm = blockIdx.x * BM;
    const int arow = t >> 1, acol = (t & 1) << 3;
    const int tx = t & 15, ty = t >> 4;
    const bool xok = (bm + arow) < M;
    const float4 z4 = make_float4(0.f,0.f,0.f,0.f);

    float acc[8];
#pragma unroll
    for (int i = 0; i < 8; i++) acc[i] = 0.f;

    for (int k0 = 0; k0 < K; k0 += 16) {
        float4 v0 = z4, v1 = z4;
        if (xok) {
            v0 = *reinterpret_cast<const float4*>(X + (size_t)(bm+arow)*lda + k0 + acol);
            v1 = *reinterpret_cast<const float4*>(X + (size_t)(bm+arow)*lda + k0 + acol + 4);
        }
        float4 wv = z4;
        int wr = t >> 2, wc = (t & 3) << 2;
        if (t < 64) wv = *reinterpret_cast<const float4*>(W + (size_t)wr*ldw + k0 + wc);
        __syncthreads();
        As[acol+0][arow]=v0.x; As[acol+1][arow]=v0.y; As[acol+2][arow]=v0.z; As[acol+3][arow]=v0.w;
        As[acol+4][arow]=v1.x; As[acol+5][arow]=v1.y; As[acol+6][arow]=v1.z; As[acol+7][arow]=v1.w;
        if (t < 64) { Bs[wc+0][wr]=wv.x; Bs[wc+1][wr]=wv.y; Bs[wc+2][wr]=wv.z; Bs[wc+3][wr]=wv.w; }
        __syncthreads();
#pragma unroll
        for (int k = 0; k < 16; k++) {
            float b = Bs[k][tx];
            float4 a0 = *reinterpret_cast<const float4*>(&As[k][ty*8]);
            float4 a1 = *reinterpret_cast<const float4*>(&As[k][ty*8+4]);
            acc[0]=fmaf(a0.x,b,acc[0]); acc[1]=fmaf(a0.y,b,acc[1]);
            acc[2]=fmaf(a0.z,b,acc[2]); acc[3]=fmaf(a0.w,b,acc[3]);
            acc[4]=fmaf(a1.x,b,acc[4]); acc[5]=fmaf(a1.y,b,acc[5]);
            acc[6]=fmaf(a1.z,b,acc[6]); acc[7]=fmaf(a1.w,b,acc[7]);
        }
        __syncthreads();
    }
    float bb = bias[tx];
#pragma unroll
    for (int i = 0; i < 8; i++) {
        int r = bm + ty*8 + i;
        if (r >= M) continue;
        float v = acc[i] + bb;
        if (relu) v = fmaxf(v, 0.f);
        v *= scale;
        C[(size_t)r*16 + tx] = v;
        if (C2) C2[(size_t)r*16 + tx] = v;
    }
}

/* ---------------- fused tail: layer3+merge+layer4, dual-store p ------------ */
__global__ __launch_bounds__(256,2)
void k_tail(const __nv_bfloat16* __restrict__ Xh, const __nv_bfloat16* __restrict__ Xl,
            const float* __restrict__ W3, const float* __restrict__ b3,
            const float* __restrict__ W4, const float* __restrict__ b4,
            float* __restrict__ out_p, float* __restrict__ pal)
{
    __shared__ __align__(16) float As[16][BM+4];
    __shared__ float Bs[16][17];
    __shared__ float Z[128][17];
    const int t = threadIdx.x;
    const int base = blockIdx.x * 128;
    const int arow = t >> 1, acol = (t & 1) << 3;
    const int tx = t & 15, ty = t >> 4;

#pragma unroll
    for (int d = 0; d < 2; d++) {
        float acc[8];
#pragma unroll
        for (int i = 0; i < 8; i++) acc[i] = 0.f;
        const size_t roff = (size_t)(base + arow + d*Ee) * 256;

        for (int k0 = 0; k0 < 256; k0 += 16) {
            uint4 uh = *reinterpret_cast<const uint4*>(Xh + roff + k0 + acol);
            uint4 ul = *reinterpret_cast<const uint4*>(Xl + roff + k0 + acol);
            float4 wv = make_float4(0.f,0.f,0.f,0.f);
            int wr = t >> 2, wc = (t & 3) << 2;
            if (t < 64) wv = *reinterpret_cast<const float4*>(W3 + (size_t)wr*256 + k0 + wc);
            __syncthreads();
            {
                const unsigned* ph = reinterpret_cast<const unsigned*>(&uh);
                const unsigned* pl = reinterpret_cast<const unsigned*>(&ul);
#pragma unroll
                for (int q = 0; q < 4; q++) {
                    __nv_bfloat162 hh = *reinterpret_cast<const __nv_bfloat162*>(&ph[q]);
                    __nv_bfloat162 ll = *reinterpret_cast<const __nv_bfloat162*>(&pl[q]);
                    float2 fh = __bfloat1622float2(hh);
                    float2 fl = __bfloat1622float2(ll);
                    As[acol + 2*q    ][arow] = fh.x + fl.x;
                    As[acol + 2*q + 1][arow] = fh.y + fl.y;
                }
            }
            if (t < 64) { Bs[wc+0][wr]=wv.x; Bs[wc+1][wr]=wv.y; Bs[wc+2][wr]=wv.z; Bs[wc+3][wr]=wv.w; }
            __syncthreads();
#pragma unroll
            for (int k = 0; k < 16; k++) {
                float b = Bs[k][tx];
                float4 a0 = *reinterpret_cast<const float4*>(&As[k][ty*8]);
                float4 a1 = *reinterpret_cast<const float4*>(&As[k][ty*8+4]);
                acc[0]=fmaf(a0.x,b,acc[0]); acc[1]=fmaf(a0.y,b,acc[1]);
                acc[2]=fmaf(a0.z,b,acc[2]); acc[3]=fmaf(a0.w,b,acc[3]);
                acc[4]=fmaf(a1.x,b,acc[4]); acc[5]=fmaf(a1.y,b,acc[5]);
                acc[6]=fmaf(a1.z,b,acc[6]); acc[7]=fmaf(a1.w,b,acc[7]);
            }
        }
        float bb = b3[tx];
#pragma unroll
        for (int i = 0; i < 8; i++) {
            float v = fmaxf(acc[i] + bb, 0.f);
            if (d == 0) Z[ty*8 + i][tx] = v;
            else        Z[ty*8 + i][tx] += v;
        }
        __syncthreads();
    }

    float w4r[16];
#pragma unroll
    for (int k = 0; k < 16; k++) w4r[k] = W4[t*16 + k];
    const float bb4 = 2.f * b4[t];
    const float sc = 0.5f / (float)Ee;
    for (int r = 0; r < 128; r++) {
        float s = bb4;
#pragma unroll
        for (int k = 0; k < 16; k++) s = fmaf(Z[r][k], w4r[k], s);
        s *= sc;
        const size_t off = (size_t)(base + r)*256 + t;
        out_p[off] = s;
        pal[off]   = s;
    }
}

/* ---------------- GRU elementwise ------------------------------------------ */
__global__ void k_gru(const float* __restrict__ hprev, float* __restrict__ out_h) {
    int idx = blockIdx.x*blockDim.x + threadIdx.x;
    if (idx >= Nn*Hh) return;
    int n = idx / Hh, d = idx % Hh;
    const float* gi = g_gi + n*G3;
    const float* gh = g_gh + n*G3;
    float r = 1.f/(1.f + expf(-(gi[d]       + gh[d])));
    float z = 1.f/(1.f + expf(-(gi[Hh+d]    + gh[Hh+d])));
    float t = tanhf(gi[2*Hh+d] + r*gh[2*Hh+d]);
    float h = (1.f - z)*t + z*hprev[idx];
    g_h[idx] = h;
    out_h[idx] = h;
}

/* ---------------- p-layer0: relu(hA[a]+hB[b]+b0) -> split bf16 ------------- */
__global__ void k_edge0(const int* __restrict__ edges, const float* __restrict__ b0) {
    int idx = blockIdx.x*blockDim.x + threadIdx.x;
    if (idx >= E2*32) return;
    int r = idx >> 5;
    int c = (idx & 31) << 2;
    int e = (r < Ee) ? r : r - Ee;
    int i = edges[2*e], j = edges[2*e+1];
    int na = (r < Ee) ? i : j;
    int nb = (r < Ee) ? j : i;
    float4 a = *reinterpret_cast<const float4*>(&g_hA[na*Hh + c]);
    float4 b = *reinterpret_cast<const float4*>(&g_hB[nb*Hh + c]);
    float4 bb = *reinterpret_cast<const float4*>(&b0[c]);
    float v0 = fmaxf(a.x + b.x + bb.x, 0.f);
    float v1 = fmaxf(a.y + b.y + bb.y, 0.f);
    float v2 = fmaxf(a.z + b.z + bb.z, 0.f);
    float v3 = fmaxf(a.w + b.w + bb.w, 0.f);
    unsigned h01, l01, h23, l23;
    split2(v0, v1, h01, l01);
    split2(v2, v3, h23, l23);
    size_t base = (size_t)r*Hh + c;
    *reinterpret_cast<unsigned*>(&g_a0h[base])     = h01;
    *reinterpret_cast<unsigned*>(&g_a0h[base + 2]) = h23;
    *reinterpret_cast<unsigned*>(&g_a0l[base])     = l01;
    *reinterpret_cast<unsigned*>(&g_a0l[base + 2]) = l23;
}

/* ---------------- message update, 4 lanes/edge, float4 loads --------------- */
__global__ void k_msg(const int* __restrict__ edges, const float* __restrict__ u,
                      const float* __restrict__ p, int cur, int nxt) {
    int gt = blockIdx.x*blockDim.x + threadIdx.x;
    int w = gt >> 2;                        /* 4 lanes per edge */
    if (w >= Ee) return;
    if (!g_isrep[w]) return;
    const unsigned gmask = 0xFu << (threadIdx.x & 28);
    const int l = threadIdx.x & 3;
    const float* S  = g_S + cur*Nn*Aa;
    float*       Sn = g_S + nxt*Nn*Aa;
    int i = edges[2*w], j = edges[2*w+1];
    const int c4 = 4*l;

    float4 Mi = *reinterpret_cast<const float4*>(&g_M[(w*2 + 0)*Aa + c4]);
    float4 Mj = *reinterpret_cast<const float4*>(&g_M[(w*2 + 1)*Aa + c4]);
    float4 ui = *reinterpret_cast<const float4*>(&u[i*Aa + c4]);
    float4 Si = *reinterpret_cast<const float4*>(&S[i*Aa + c4]);
    float4 uj = *reinterpret_cast<const float4*>(&u[j*Aa + c4]);
    float4 Sj = *reinterpret_cast<const float4*>(&S[j*Aa + c4]);

    float bi[4] = {ui.x + Si.x - Mi.x, ui.y + Si.y - Mi.y,
                   ui.z + Si.z - Mi.z, ui.w + Si.w - Mi.w};
    float bj[4] = {uj.x + Sj.x - Mj.x, uj.y + Sj.y - Mj.y,
                   uj.z + Sj.z - Mj.z, uj.w + Sj.w - Mj.w};

    const float* pe = p + (size_t)w*256;
    float mtj[4]    = {-FLT_MAX, -FLT_MAX, -FLT_MAX, -FLT_MAX};
    float colmax[4] = {-FLT_MAX, -FLT_MAX, -FLT_MAX, -FLT_MAX};
#pragma unroll
    for (int a2 = 0; a2 < 16; a2++) {
        float4 pr = *reinterpret_cast<const float4*>(&pe[a2*16 + c4]);
        float bia = __shfl_sync(gmask, bi[a2 & 3], a2 >> 2, 4);
        mtj[0] = fmaxf(mtj[0], pr.x + bia);
        mtj[1] = fmaxf(mtj[1], pr.y + bia);
        mtj[2] = fmaxf(mtj[2], pr.z + bia);
        mtj[3] = fmaxf(mtj[3], pr.w + bia);
        colmax[0] = fmaxf(colmax[0], pr.x);
        colmax[1] = fmaxf(colmax[1], pr.y);
        colmax[2] = fmaxf(colmax[2], pr.z);
        colmax[3] = fmaxf(colmax[3], pr.w);
    }
    float mti[4];
#pragma unroll
    for (int q = 0; q < 4; q++) mti[q] = colmax[q] + bj[q];

    float s1 = (mtj[0] + mtj[1]) + (mtj[2] + mtj[3]);
    float s2 = (mti[0] + mti[1]) + (mti[2] + mti[3]);
    s1 += __shfl_xor_sync(gmask, s1, 1, 4);
    s1 += __shfl_xor_sync(gmask, s1, 2, 4);
    s2 += __shfl_xor_sync(gmask, s2, 1, 4);
    s2 += __shfl_xor_sync(gmask, s2, 2, 4);
    const float m1 = s1 * (1.f/16.f), m2 = s2 * (1.f/16.f);
#pragma unroll
    for (int q = 0; q < 4; q++) { mtj[q] -= m1; mti[q] -= m2; }

    *reinterpret_cast<float4*>(&g_M[(w*2 + 1)*Aa + c4]) = make_float4(mtj[0],mtj[1],mtj[2],mtj[3]);
    *reinterpret_cast<float4*>(&g_M[(w*2 + 0)*Aa + c4]) = make_float4(mti[0],mti[1],mti[2],mti[3]);
#pragma unroll
    for (int q = 0; q < 4; q++) {
        atomicAdd(&Sn[i*Aa + c4 + q], mti[q]);
        atomicAdd(&Sn[j*Aa + c4 + q], mtj[q]);
    }
}

/* ---------------- per-node argmax (aidx only) ------------------------------- */
__global__ void k_argmax(const float* __restrict__ u, int sb, int ab) {
    int idx = blockIdx.x*blockDim.x + threadIdx.x;
    if (idx >= Nn) return;
    const float* S = g_S + sb*Nn*Aa;
    float best = -FLT_MAX; int bi = 0;
#pragma unroll
    for (int a = 0; a < Aa; a++) {
        float v = u[idx*Aa + a] + S[idx*Aa + a];
        if (v > best) { best = v; bi = a; }
    }
    g_aidx[ab][idx] = bi;
}

/* ---------------- zero one S buffer ----------------------------------------- */
__global__ void k_zero(int sb) {
    int idx = blockIdx.x*blockDim.x + threadIdx.x;
    if (idx < Nn*Aa) g_S[sb*Nn*Aa + idx] = 0.f;
}

/* ---------------- q partial sums + fused last-block final reduce ----------- */
__global__ void k_qstep(const int* __restrict__ edges, const float* __restrict__ u,
                        const float* __restrict__ p, int ab) {
    __shared__ float red[256];
    __shared__ int lastdone;
    const int* aidx = g_aidx[ab];
    int tid = threadIdx.x, bid = blockIdx.x;
    int gt = bid*256 + tid;
    float local = 0.f;
    for (int n = gt; n < Nn; n += 64*256) local += u[n*Aa + aidx[n]];
    for (int e = gt; e < Ee; e += 64*256) {
        int i = edges[2*e], j = edges[2*e+1];
        local += p[(size_t)e*256 + aidx[i]*Aa + aidx[j]];
    }
    red[tid] = local;
    __syncthreads();
    for (int s = 128; s > 0; s >>= 1) {
        if (tid < s) red[tid] += red[tid + s];
        __syncthreads();
    }
    if (tid == 0) {
        g_part[bid] = red[0];
        __threadfence();
        int done = atomicAdd(&g_qctr, 1);
        lastdone = (done == 63) ? 1 : 0;
    }
    __syncthreads();
    if (!lastdone) return;
    __shared__ int better;
    if (tid == 0) {
        float q = 0.f;
        for (int k = 0; k < 64; k++) q += g_part[k];
        if (q > g_qmax) { g_qmax = q; better = 1; } else better = 0;
        g_qctr = 0;
    }
    __syncthreads();
    if (better) {
        for (int n = tid; n < Nn; n += 256) g_best[n] = g_aidx[ab][n];
    }
}

/* ---------------- finalize --------------------------------------------------- */
__global__ void k_final(float* __restrict__ out) {
    int idx = blockIdx.x*blockDim.x + threadIdx.x;
    if (idx >= Nn*Aa) return;
    int n = idx >> 4, a = idx & 15;
    out[idx] = (g_best[n] == a) ? 1.f : 0.f;
    if (idx == 0) out[Nn*Aa] = g_qmax;
}

/* ---------------- host ------------------------------------------------------- */
static inline void gemm(cudaStream_t st, const float* X, int lda, const float* W, int ldw,
                        const float* b, float* C, int M, int N, int K,
                        int relu, float scale, float bias_mult, int vec_store) {
    dim3 grid(N/BN, (M + BM - 1)/BM);
    k_gemm128<<<grid, 256, 0, st>>>(X, lda, W, ldw, b, C, M, N, K, relu, scale, bias_mult, vec_store);
}

extern "C" void kernel_launch(void* const* d_in, const int* in_sizes, int n_in,
                              void* d_out, int out_size) {
    const float* x    = (const float*)d_in[0];
    const float* pa   = (const float*)d_in[1];
    const float* st   = (const float*)d_in[2];
    const int*   edges= (const int*)  d_in[3];
    const float* wih  = (const float*)d_in[4];
    const float* whh  = (const float*)d_in[5];
    const float* bih  = (const float*)d_in[6];
    const float* bhh  = (const float*)d_in[7];
    const float* uW0  = (const float*)d_in[8];   const float* ub0 = (const float*)d_in[9];
    const float* uW1  = (const float*)d_in[10];  const float* ub1 = (const float*)d_in[11];
    const float* uW2  = (const float*)d_in[12];  const float* ub2 = (const float*)d_in[13];
    const float* pW0  = (const float*)d_in[14];  const float* pb0 = (const float*)d_in[15];
    const float* pW1  = (const float*)d_in[16];  const float* pb1 = (const float*)d_in[17];
    const float* pW2  = (const float*)d_in[18];  const float* pb2 = (const float*)d_in[19];
    const float* pW3  = (const float*)d_in[20];  const float* pb3 = (const float*)d_in[21];
    const float* pW4  = (const float*)d_in[22];  const float* pb4 = (const float*)d_in[23];

    float* out   = (float*)d_out;
    float* out_u = out + Nn*Aa + 1;
    float* out_p = out_u + Nn*Aa;
    float* out_h = out_p + (size_t)Ee*Aa*Aa;

    float *gi_, *gh_, *h_, *hA_, *hB_, *ua_, *ub_, *ual_, *pal_;
    __nv_bfloat16 *a0h_, *a0l_, *a1h_, *a1l_, *a2h_, *a2l_, *w1h_, *w1l_, *w2h_, *w2l_;
    cudaGetSymbolAddress((void**)&gi_,   g_gi);
    cudaGetSymbolAddress((void**)&gh_,   g_gh);
    cudaGetSymbolAddress((void**)&h_,    g_h);
    cudaGetSymbolAddress((void**)&hA_,   g_hA);
    cudaGetSymbolAddress((void**)&hB_,   g_hB);
    cudaGetSymbolAddress((void**)&ua_,   g_ua);
    cudaGetSymbolAddress((void**)&ub_,   g_ub);
    cudaGetSymbolAddress((void**)&ual_,  g_ual);
    cudaGetSymbolAddress((void**)&pal_,  g_pal);
    cudaGetSymbolAddress((void**)&a0h_,  g_a0h);
    cudaGetSymbolAddress((void**)&a0l_,  g_a0l);
    cudaGetSymbolAddress((void**)&a1h_,  g_a1h);
    cudaGetSymbolAddress((void**)&a1l_,  g_a1l);
    cudaGetSymbolAddress((void**)&a2h_,  g_a2h);
    cudaGetSymbolAddress((void**)&a2l_,  g_a2l);
    cudaGetSymbolAddress((void**)&w1h_,  g_w1h);
    cudaGetSymbolAddress((void**)&w1l_,  g_w1l);
    cudaGetSymbolAddress((void**)&w2h_,  g_w2h);
    cudaGetSymbolAddress((void**)&w2l_,  g_w2l);

    static cudaStream_t s1 = 0, s2 = 0, s3 = 0;
    static cudaEvent_t e0 = 0, e_gh, e_gru, e_u, e_hb, e_s1, e_w, e_fork3;
    static cudaEvent_t evM[NITER], evZ[NITER], evA[NITER], evQ[NITER];
    if (!e0) {
        cudaStreamCreateWithFlags(&s1, cudaStreamNonBlocking);
        cudaStreamCreateWithFlags(&s2, cudaStreamNonBlocking);
        cudaStreamCreateWithFlags(&s3, cudaStreamNonBlocking);
        cudaEventCreateWithFlags(&e0,   cudaEventDisableTiming);
        cudaEventCreateWithFlags(&e_gh, cudaEventDisableTiming);
        cudaEventCreateWithFlags(&e_gru,cudaEventDisableTiming);
        cudaEventCreateWithFlags(&e_u,  cudaEventDisableTiming);
        cudaEventCreateWithFlags(&e_hb, cudaEventDisableTiming);
        cudaEventCreateWithFlags(&e_s1, cudaEventDisableTiming);
        cudaEventCreateWithFlags(&e_w,  cudaEventDisableTiming);
        cudaEventCreateWithFlags(&e_fork3, cudaEventDisableTiming);
        for (int t = 0; t < NITER; t++) {
            cudaEventCreateWithFlags(&evM[t], cudaEventDisableTiming);
            cudaEventCreateWithFlags(&evZ[t], cudaEventDisableTiming);
            cudaEventCreateWithFlags(&evA[t], cudaEventDisableTiming);
            cudaEventCreateWithFlags(&evQ[t], cudaEventDisableTiming);
        }
    }

    /* fork */
    cudaEventRecord(e0, 0);
    cudaStreamWaitEvent(s1, e0, 0);
    cudaStreamWaitEvent(s2, e0, 0);
    cudaStreamWaitEvent(s3, e0, 0);

    /* s1: MP state init + duplicate-edge dedup */
    k_init<<<1024, 256, 0, s1>>>();
    k_clearmap<<<(Ee + 255)/256, 256, 0, s1>>>(edges);
    k_mapbuild<<<(Ee + 255)/256, 256, 0, s1>>>(edges);
    k_isrep<<<(Ee + 255)/256, 256, 0, s1>>>(edges);
    cudaEventRecord(e_s1, s1);

    /* s3: weight splits */
    k_wsplit<<<(256*Hh + 255)/256, 256, 0, s3>>>(pW1, 256*Hh, w1h_, w1l_);
    k_wsplit<<<(256*256 + 255)/256, 256, 0, s3>>>(pW2, 256*256, w2h_, w2l_);
    cudaEventRecord(e_w, s3);

    /* s2: gh GEMM */
    gemm(s2, st, Hh, whh, Hh, bhh, gh_, Nn, G3, Hh, 0, 1.f, 1.f, 1);
    cudaEventRecord(e_gh, s2);

    /* 0: gi GEMM with fused concat, then GRU */
    {
        dim3 grid(G3/BN, (Nn + BM - 1)/BM);
        k_gemmGI<<<grid, 256>>>(x, pa, wih, IN_DIM, bih, gi_, Nn, G3, IN_DIM);
    }
    cudaStreamWaitEvent(0, e_gh, 0);
    k_gru<<<(Nn*Hh + 255)/256, 256>>>(st, out_h);
    cudaEventRecord(e_gru, 0);

    /* s2: utility MLP (dual-store u into out_u and aligned g_ual) */
    cudaStreamWaitEvent(s2, e_gru, 0);
    gemm(s2, h_,  Hh,  uW0, Hh,  ub0, ua_, Nn, 256, Hh,  1, 1.f, 1.f, 1);
    gemm(s2, ua_, 256, uW1, 256, ub1, ub_, Nn, 256, 256, 1, 1.f, 1.f, 1);
    k_gemm16<<<(Nn + BM - 1)/BM, 256, 0, s2>>>(ub_, 256, uW2, 256, ub2, out_u, ual_, Nn, 256, 0, 1.f/(float)Nn);
    cudaEventRecord(e_u, s2);

    /* s3: hB GEMM */
    cudaStreamWaitEvent(s3, e_gru, 0);
    gemm(s3, h_, Hh, pW0 + Hh, 2*Hh, pb0, hB_, Nn, Hh, Hh, 0, 1.f, 0.f, 1);
    cudaEventRecord(e_hb, s3);

    /* 0: hA GEMM, edge0 (split), tensor layers 1-2, fused tail (dual-store p) */
    gemm(0, h_, Hh, pW0, 2*Hh, pb0, hA_, Nn, Hh, Hh, 0, 1.f, 0.f, 1);
    cudaStreamWaitEvent(0, e_hb, 0);
    k_edge0<<<(E2*32 + 255)/256, 256>>>(edges, pb0);
    cudaStreamWaitEvent(0, e_w, 0);
    {
        dim3 g1(256/TBN, E2/TBM);
        k_tgemm<<<g1, 256>>>(a0h_, a0l_, w1h_, w1l_, pb1, E2, 256, Hh,  a1h_, a1l_);
        k_tgemm<<<g1, 256>>>(a1h_, a1l_, w2h_, w2l_, pb2, E2, 256, 256, a2h_, a2l_);
    }
    k_tail<<<Ee/128, 256>>>(a2h_, a2l_, pW3, pb3, pW4, pb4, out_p, pal_);

    /* join: msg needs u, p, isrep, S zeroed */
    cudaStreamWaitEvent(0, e_u, 0);
    cudaStreamWaitEvent(0, e_s1, 0);
    /* fence s3 past its front work before MP uses it for qstep */
    cudaEventRecord(e_fork3, 0);
    cudaStreamWaitEvent(s3, e_fork3, 0);

    /* MP: msg-only critical path on stream 0 (aligned u/p copies).
       s2: argmax (fast) + zero recycled S buffer.
       s3: qstep (heavy, deterministic reduce), off critical path. */
    for (int t = 0; t < NITER; t++) {
        int cur = t % 3, nxt = (t + 1) % 3, ab = t & 1;
        if (t >= 2) cudaStreamWaitEvent(0, evZ[t-2], 0);
        k_msg<<<(Ee*4 + 255)/256, 256>>>(edges, ual_, pal_, cur, nxt);
        cudaEventRecord(evM[t], 0);
        cudaStreamWaitEvent(s2, evM[t], 0);
        if (t >= 2) cudaStreamWaitEvent(s2, evQ[t-2], 0);  /* aidx[ab] reuse */
        k_argmax<<<(Nn + 255)/256, 256, 0, s2>>>(ual_, nxt, ab);
        cudaEventRecord(evA[t], s2);
        k_zero<<<(Nn*Aa + 255)/256, 256, 0, s2>>>(cur);
        cudaEventRecord(evZ[t], s2);
        cudaStreamWaitEvent(s3, evA[t], 0);
        k_qstep<<<64, 256, 0, s3>>>(edges, ual_, pal_, ab);
        cudaEventRecord(evQ[t], s3);
    }
    /* join ALL side streams back into the capture stream */
    cudaStreamWaitEvent(0, evQ[NITER-1], 0);   /* s3 tail */
    cudaStreamWaitEvent(0, evZ[NITER-1], 0);   /* s2 tail (covers argmax+zero) */

    k_final<<<(Nn*Aa + 255)/256, 256>>>(out);
}

// round 17
// speedup vs baseline: 1.0579x; 1.0579x over previous
#include <cuda_runtime.h>
#include <cuda_bf16.h>
#include <math.h>
#include <float.h>

#define Nn   2000
#define Aa   16
#define OBSd 64
#define Hh   128
#define Ee   16000
#define NITER 8
#define IN_DIM 80
#define G3    384
#define E2    (2*Ee)

/* ---------------- scratch (static device globals) ------------------------ */
__device__ __align__(16) float g_gi[Nn*G3];
__device__ __align__(16) float g_gh[Nn*G3];
__device__ __align__(16) float g_h[Nn*Hh];
__device__ __align__(16) float g_hA[Nn*Hh];
__device__ __align__(16) float g_hB[Nn*Hh];
__device__ __align__(16) float g_ua[Nn*256];
__device__ __align__(16) float g_ub[Nn*256];
__device__ __align__(16) __nv_bfloat16 g_a0h[(size_t)E2*Hh];
__device__ __align__(16) __nv_bfloat16 g_a0l[(size_t)E2*Hh];
__device__ __align__(16) __nv_bfloat16 g_a1h[(size_t)E2*256];
__device__ __align__(16) __nv_bfloat16 g_a1l[(size_t)E2*256];
__device__ __align__(16) __nv_bfloat16 g_a2h[(size_t)E2*256];
__device__ __align__(16) __nv_bfloat16 g_a2l[(size_t)E2*256];
__device__ __align__(16) __nv_bfloat16 g_w1h[256*Hh],  g_w1l[256*Hh];
__device__ __align__(16) __nv_bfloat16 g_w2h[256*256], g_w2l[256*256];
__device__ __align__(16) float g_M[Ee*2*Aa];
__device__ __align__(16) float g_S[3*Nn*Aa];     /* triple-buffered */
__device__ int   g_map[Nn*Nn];
__device__ int   g_isrep[Ee];
__device__ int   g_aidx[2][Nn];
__device__ int   g_best[Nn];
__device__ float g_part[64];
__device__ int   g_qctr;
__device__ float g_qmax;

/* ---------------- bf16 split helper ---------------------------------------- */
__device__ __forceinline__ void split2(float v0, float v1, unsigned& h, unsigned& l) {
    __nv_bfloat162 hh = __floats2bfloat162_rn(v0, v1);
    float r0 = v0 - __bfloat162float(hh.x);
    float r1 = v1 - __bfloat162float(hh.y);
    __nv_bfloat162 ll = __floats2bfloat162_rn(r0, r1);
    h = *reinterpret_cast<unsigned*>(&hh);
    l = *reinterpret_cast<unsigned*>(&ll);
}

/* ---------------- cp.async helpers ------------------------------------------ */
__device__ __forceinline__ unsigned smem_u32(const void* p) {
    return (unsigned)__cvta_generic_to_shared(p);
}
#define CP16(dst, src) \
    asm volatile("cp.async.cg.shared.global [%0], [%1], 16;" :: "r"(dst), "l"(src))
#define CP_COMMIT() asm volatile("cp.async.commit_group;")
#define CP_WAIT(n)  asm volatile("cp.async.wait_group %0;" :: "n"(n))

/* ---------------- init ------------------------------------------------------ */
__global__ void k_init() {
    int idx = blockIdx.x*blockDim.x + threadIdx.x;
    int stride = gridDim.x*blockDim.x;
    for (int i = idx; i < Ee*2*Aa; i += stride) g_M[i]   = 0.f;
    for (int i = idx; i < 3*Nn*Aa; i += stride) g_S[i]   = 0.f;
    for (int i = idx; i < Nn; i += stride)      g_best[i] = -1;
    if (idx == 0) { g_qmax = 0.f; g_qctr = 0; }
}

__global__ void k_clearmap(const int* __restrict__ edges) {
    int e = blockIdx.x*blockDim.x + threadIdx.x;
    if (e >= Ee) return;
    g_map[edges[2*e]*Nn + edges[2*e+1]] = 0x7fffffff;
}

__global__ void k_mapbuild(const int* __restrict__ edges) {
    int e = blockIdx.x*blockDim.x + threadIdx.x;
    if (e >= Ee) return;
    atomicMin(&g_map[edges[2*e]*Nn + edges[2*e+1]], e);
}

__global__ void k_isrep(const int* __restrict__ edges) {
    int e = blockIdx.x*blockDim.x + threadIdx.x;
    if (e >= Ee) return;
    g_isrep[e] = (g_map[edges[2*e]*Nn + edges[2*e+1]] == e) ? 1 : 0;
}

/* ---------------- weight split --------------------------------------------- */
__global__ void k_wsplit(const float* __restrict__ W, int n,
                         __nv_bfloat16* __restrict__ Wh, __nv_bfloat16* __restrict__ Wl) {
    int i = blockIdx.x*blockDim.x + threadIdx.x;
    if (i >= n) return;
    float v = W[i];
    __nv_bfloat16 h = __float2bfloat16(v);
    Wh[i] = h;
    Wl[i] = __float2bfloat16(v - __bfloat162float(h));
}

/* ---------------- 128x128x8 double-buffered SGEMM (fp32) ------------------- */
#define BM 128
#define BN 128
#define BK 8

__global__ __launch_bounds__(256,2)
void k_gemm128(const float* __restrict__ X, int lda,
               const float* __restrict__ W, int ldw,
               const float* __restrict__ bias, float* __restrict__ C,
               int M, int N, int K, int relu, float scale, float bias_mult,
               int vec_store)
{
    __shared__ __align__(16) float As[2][BK][BM+4];
    __shared__ __align__(16) float Bs[2][BK][BN+4];
    const int t   = threadIdx.x;
    const int bm  = blockIdx.y * BM;
    const int bn  = blockIdx.x * BN;
    const int lrow = t >> 1;
    const int lcol = (t & 1) << 2;
    const int tx = t & 15, ty = t >> 4;
    const int cx0 = tx << 2, cx1 = 64 + (tx << 2);
    const int ry0 = ty << 2, ry1 = 64 + (ty << 2);

    float acc[8][8];
#pragma unroll
    for (int i = 0; i < 8; i++)
#pragma unroll
        for (int j = 0; j < 8; j++) acc[i][j] = 0.f;

    const bool xok = (bm + lrow) < M;
    const bool wok = (bn + lrow) < N;
    const float* Xp = X + (size_t)(bm + lrow)*lda + lcol;
    const float* Wp = W + (size_t)(bn + lrow)*ldw + lcol;
    const float4 z4 = make_float4(0.f,0.f,0.f,0.f);

    float4 xa = xok ? *reinterpret_cast<const float4*>(Xp) : z4;
    float4 wa = wok ? *reinterpret_cast<const float4*>(Wp) : z4;
    As[0][lcol+0][lrow]=xa.x; As[0][lcol+1][lrow]=xa.y; As[0][lcol+2][lrow]=xa.z; As[0][lcol+3][lrow]=xa.w;
    Bs[0][lcol+0][lrow]=wa.x; Bs[0][lcol+1][lrow]=wa.y; Bs[0][lcol+2][lrow]=wa.z; Bs[0][lcol+3][lrow]=wa.w;
    __syncthreads();

    int buf = 0;
    for (int k0 = 0; k0 < K; k0 += BK) {
        const bool more = (k0 + BK) < K;
        float4 xn = z4, wn = z4;
        if (more) {
            if (xok) xn = *reinterpret_cast<const float4*>(Xp + k0 + BK);
            if (wok) wn = *reinterpret_cast<const float4*>(Wp + k0 + BK);
        }
#pragma unroll
        for (int k = 0; k < BK; k++) {
            float4 a0 = *reinterpret_cast<const float4*>(&As[buf][k][ry0]);
            float4 a1 = *reinterpret_cast<const float4*>(&As[buf][k][ry1]);
            float4 b0 = *reinterpret_cast<const float4*>(&Bs[buf][k][cx0]);
            float4 b1 = *reinterpret_cast<const float4*>(&Bs[buf][k][cx1]);
            float ar[8] = {a0.x,a0.y,a0.z,a0.w,a1.x,a1.y,a1.z,a1.w};
            float br[8] = {b0.x,b0.y,b0.z,b0.w,b1.x,b1.y,b1.z,b1.w};
#pragma unroll
            for (int i = 0; i < 8; i++)
#pragma unroll
                for (int j = 0; j < 8; j++)
                    acc[i][j] = fmaf(ar[i], br[j], acc[i][j]);
        }
        if (more) {
            int nb = buf ^ 1;
            As[nb][lcol+0][lrow]=xn.x; As[nb][lcol+1][lrow]=xn.y; As[nb][lcol+2][lrow]=xn.z; As[nb][lcol+3][lrow]=xn.w;
            Bs[nb][lcol+0][lrow]=wn.x; Bs[nb][lcol+1][lrow]=wn.y; Bs[nb][lcol+2][lrow]=wn.z; Bs[nb][lcol+3][lrow]=wn.w;
            __syncthreads();
            buf = nb;
        }
    }

    float4 bv0 = *reinterpret_cast<const float4*>(&bias[bn + cx0]);
    float4 bv1 = *reinterpret_cast<const float4*>(&bias[bn + cx1]);
#pragma unroll
    for (int ii = 0; ii < 8; ii++) {
        int r = bm + ((ii < 4) ? (ry0 + ii) : (ry1 + ii - 4));
        if (r >= M) continue;
        float o[8];
        o[0]=acc[ii][0]+bias_mult*bv0.x; o[1]=acc[ii][1]+bias_mult*bv0.y;
        o[2]=acc[ii][2]+bias_mult*bv0.z; o[3]=acc[ii][3]+bias_mult*bv0.w;
        o[4]=acc[ii][4]+bias_mult*bv1.x; o[5]=acc[ii][5]+bias_mult*bv1.y;
        o[6]=acc[ii][6]+bias_mult*bv1.z; o[7]=acc[ii][7]+bias_mult*bv1.w;
        if (relu) {
#pragma unroll
            for (int j = 0; j < 8; j++) o[j] = fmaxf(o[j], 0.f);
        }
#pragma unroll
        for (int j = 0; j < 8; j++) o[j] *= scale;
        if (vec_store) {
            *reinterpret_cast<float4*>(&C[(size_t)r*N + bn + cx0]) = make_float4(o[0],o[1],o[2],o[3]);
            *reinterpret_cast<float4*>(&C[(size_t)r*N + bn + cx1]) = make_float4(o[4],o[5],o[6],o[7]);
        } else {
            float* c0 = &C[(size_t)r*N + bn + cx0];
            float* c1 = &C[(size_t)r*N + bn + cx1];
            c0[0]=o[0]; c0[1]=o[1]; c0[2]=o[2]; c0[3]=o[3];
            c1[0]=o[4]; c1[1]=o[5]; c1[2]=o[6]; c1[3]=o[7];
        }
    }
}

/* ---------------- gi GEMM with fused concat loader ------------------------- */
__device__ __forceinline__ float4 ld_concat(const float* __restrict__ x,
                                            const float* __restrict__ pa,
                                            int row, int c) {
    return (c < OBSd) ? *reinterpret_cast<const float4*>(x + (size_t)row*OBSd + c)
                      : *reinterpret_cast<const float4*>(pa + (size_t)row*Aa + (c - OBSd));
}

__global__ __launch_bounds__(256,2)
void k_gemmGI(const float* __restrict__ x, const float* __restrict__ pa,
              const float* __restrict__ W, int ldw,
              const float* __restrict__ bias, float* __restrict__ C,
              int M, int N, int K)
{
    __shared__ __align__(16) float As[2][BK][BM+4];
    __shared__ __align__(16) float Bs[2][BK][BN+4];
    const int t   = threadIdx.x;
    const int bm  = blockIdx.y * BM;
    const int bn  = blockIdx.x * BN;
    const int lrow = t >> 1;
    const int lcol = (t & 1) << 2;
    const int tx = t & 15, ty = t >> 4;
    const int cx0 = tx << 2, cx1 = 64 + (tx << 2);
    const int ry0 = ty << 2, ry1 = 64 + (ty << 2);

    float acc[8][8];
#pragma unroll
    for (int i = 0; i < 8; i++)
#pragma unroll
        for (int j = 0; j < 8; j++) acc[i][j] = 0.f;

    const bool xok = (bm + lrow) < M;
    const bool wok = (bn + lrow) < N;
    const int arow = bm + lrow;
    const float* Wp = W + (size_t)(bn + lrow)*ldw + lcol;
    const float4 z4 = make_float4(0.f,0.f,0.f,0.f);

    float4 xa = xok ? ld_concat(x, pa, arow, lcol) : z4;
    float4 wa = wok ? *reinterpret_cast<const float4*>(Wp) : z4;
    As[0][lcol+0][lrow]=xa.x; As[0][lcol+1][lrow]=xa.y; As[0][lcol+2][lrow]=xa.z; As[0][lcol+3][lrow]=xa.w;
    Bs[0][lcol+0][lrow]=wa.x; Bs[0][lcol+1][lrow]=wa.y; Bs[0][lcol+2][lrow]=wa.z; Bs[0][lcol+3][lrow]=wa.w;
    __syncthreads();

    int buf = 0;
    for (int k0 = 0; k0 < K; k0 += BK) {
        const bool more = (k0 + BK) < K;
        float4 xn = z4, wn = z4;
        if (more) {
            if (xok) xn = ld_concat(x, pa, arow, k0 + BK + lcol);
            if (wok) wn = *reinterpret_cast<const float4*>(Wp + k0 + BK);
        }
#pragma unroll
        for (int k = 0; k < BK; k++) {
            float4 a0 = *reinterpret_cast<const float4*>(&As[buf][k][ry0]);
            float4 a1 = *reinterpret_cast<const float4*>(&As[buf][k][ry1]);
            float4 b0 = *reinterpret_cast<const float4*>(&Bs[buf][k][cx0]);
            float4 b1 = *reinterpret_cast<const float4*>(&Bs[buf][k][cx1]);
            float ar[8] = {a0.x,a0.y,a0.z,a0.w,a1.x,a1.y,a1.z,a1.w};
            float br[8] = {b0.x,b0.y,b0.z,b0.w,b1.x,b1.y,b1.z,b1.w};
#pragma unroll
            for (int i = 0; i < 8; i++)
#pragma unroll
                for (int j = 0; j < 8; j++)
                    acc[i][j] = fmaf(ar[i], br[j], acc[i][j]);
        }
        if (more) {
            int nb = buf ^ 1;
            As[nb][lcol+0][lrow]=xn.x; As[nb][lcol+1][lrow]=xn.y; As[nb][lcol+2][lrow]=xn.z; As[nb][lcol+3][lrow]=xn.w;
            Bs[nb][lcol+0][lrow]=wn.x; Bs[nb][lcol+1][lrow]=wn.y; Bs[nb][lcol+2][lrow]=wn.z; Bs[nb][lcol+3][lrow]=wn.w;
            __syncthreads();
            buf = nb;
        }
    }

    float4 bv0 = *reinterpret_cast<const float4*>(&bias[bn + cx0]);
    float4 bv1 = *reinterpret_cast<const float4*>(&bias[bn + cx1]);
#pragma unroll
    for (int ii = 0; ii < 8; ii++) {
        int r = bm + ((ii < 4) ? (ry0 + ii) : (ry1 + ii - 4));
        if (r >= M) continue;
        float o[8];
        o[0]=acc[ii][0]+bv0.x; o[1]=acc[ii][1]+bv0.y;
        o[2]=acc[ii][2]+bv0.z; o[3]=acc[ii][3]+bv0.w;
        o[4]=acc[ii][4]+bv1.x; o[5]=acc[ii][5]+bv1.y;
        o[6]=acc[ii][6]+bv1.z; o[7]=acc[ii][7]+bv1.w;
        *reinterpret_cast<float4*>(&C[(size_t)r*N + bn + cx0]) = make_float4(o[0],o[1],o[2],o[3]);
        *reinterpret_cast<float4*>(&C[(size_t)r*N + bn + cx1]) = make_float4(o[4],o[5],o[6],o[7]);
    }
}

/* ---------------- split-bf16 tensor GEMM, cp.async double-buffered ---------- */
#define TBM 128
#define TBN 64
#define TBK 32

#define MMA_BF16(c, a, b) \
    asm volatile("mma.sync.aligned.m16n8k16.row.col.f32.bf16.bf16.f32 " \
        "{%0,%1,%2,%3}, {%4,%5,%6,%7}, {%8,%9}, {%0,%1,%2,%3};" \
        : "+f"((c)[0]), "+f"((c)[1]), "+f"((c)[2]), "+f"((c)[3]) \
        : "r"((a)[0]), "r"((a)[1]), "r"((a)[2]), "r"((a)[3]), "r"((b)[0]), "r"((b)[1]))

__device__ __forceinline__ unsigned lds_bf2(const __nv_bfloat16* p) {
    return *reinterpret_cast<const unsigned*>(p);
}

__global__ __launch_bounds__(256,2)
void k_tgemm(const __nv_bfloat16* __restrict__ Ah, const __nv_bfloat16* __restrict__ Al,
             const __nv_bfloat16* __restrict__ Bh, const __nv_bfloat16* __restrict__ Bl,
             const float* __restrict__ bias, int M, int N, int K,
             __nv_bfloat16* __restrict__ Ch, __nv_bfloat16* __restrict__ Cl)
{
    __shared__ __align__(16) __nv_bfloat16 sAh[2][TBM][TBK+8];
    __shared__ __align__(16) __nv_bfloat16 sAl[2][TBM][TBK+8];
    __shared__ __align__(16) __nv_bfloat16 sBh[2][TBN][TBK+8];
    __shared__ __align__(16) __nv_bfloat16 sBl[2][TBN][TBK+8];

    const int t = threadIdx.x;
    const int bm = blockIdx.y * TBM;
    const int bn = blockIdx.x * TBN;
    const int wid = t >> 5;
    const int lane = t & 31;
    const int g  = lane >> 2;
    const int tg = lane & 3;
    const int warp_m = (wid & 3) * 32;
    const int warp_n = (wid >> 2) * 32;

    float c[2][4][4];
#pragma unroll
    for (int mi = 0; mi < 2; mi++)
#pragma unroll
        for (int ni = 0; ni < 4; ni++)
#pragma unroll
            for (int q = 0; q < 4; q++) c[mi][ni][q] = 0.f;

    const int ar = t >> 1;
    const int ac = (t & 1) * 16;
    const int br = t >> 2;
    const int bc = (t & 3) * 8;

    const __nv_bfloat16* pAh = Ah + (size_t)(bm+ar)*K + ac;
    const __nv_bfloat16* pAl = Al + (size_t)(bm+ar)*K + ac;
    const __nv_bfloat16* pBh = Bh + (size_t)(bn+br)*K + bc;
    const __nv_bfloat16* pBl = Bl + (size_t)(bn+br)*K + bc;

#define LD_TILE(bb, kk) do { \
        CP16(smem_u32(&sAh[bb][ar][ac]),     pAh + (kk)); \
        CP16(smem_u32(&sAh[bb][ar][ac + 8]), pAh + (kk) + 8); \
        CP16(smem_u32(&sAl[bb][ar][ac]),     pAl + (kk)); \
        CP16(smem_u32(&sAl[bb][ar][ac + 8]), pAl + (kk) + 8); \
        CP16(smem_u32(&sBh[bb][br][bc]),     pBh + (kk)); \
        CP16(smem_u32(&sBl[bb][br][bc]),     pBl + (kk)); \
        CP_COMMIT(); \
    } while (0)

    LD_TILE(0, 0);
    int buf = 0;
    for (int kk = 0; kk < K; kk += TBK) {
        const bool more = (kk + TBK) < K;
        if (more) LD_TILE(buf ^ 1, kk + TBK);
        if (more) CP_WAIT(1); else CP_WAIT(0);
        __syncthreads();

#pragma unroll
        for (int k16 = 0; k16 < TBK; k16 += 16) {
            unsigned ah[2][4], al[2][4], bh[4][2], bl[4][2];
#pragma unroll
            for (int mi = 0; mi < 2; mi++) {
                int rb = warp_m + mi*16;
                ah[mi][0] = lds_bf2(&sAh[buf][rb+g  ][k16 + 2*tg]);
                ah[mi][1] = lds_bf2(&sAh[buf][rb+g+8][k16 + 2*tg]);
                ah[mi][2] = lds_bf2(&sAh[buf][rb+g  ][k16 + 2*tg + 8]);
                ah[mi][3] = lds_bf2(&sAh[buf][rb+g+8][k16 + 2*tg + 8]);
                al[mi][0] = lds_bf2(&sAl[buf][rb+g  ][k16 + 2*tg]);
                al[mi][1] = lds_bf2(&sAl[buf][rb+g+8][k16 + 2*tg]);
                al[mi][2] = lds_bf2(&sAl[buf][rb+g  ][k16 + 2*tg + 8]);
                al[mi][3] = lds_bf2(&sAl[buf][rb+g+8][k16 + 2*tg + 8]);
            }
#pragma unroll
            for (int ni = 0; ni < 4; ni++) {
                int cb = warp_n + ni*8;
                bh[ni][0] = lds_bf2(&sBh[buf][cb+g][k16 + 2*tg]);
                bh[ni][1] = lds_bf2(&sBh[buf][cb+g][k16 + 2*tg + 8]);
                bl[ni][0] = lds_bf2(&sBl[buf][cb+g][k16 + 2*tg]);
                bl[ni][1] = lds_bf2(&sBl[buf][cb+g][k16 + 2*tg + 8]);
            }
#pragma unroll
            for (int mi = 0; mi < 2; mi++)
#pragma unroll
                for (int ni = 0; ni < 4; ni++) {
                    MMA_BF16(c[mi][ni], ah[mi], bh[ni]);
                    MMA_BF16(c[mi][ni], ah[mi], bl[ni]);
                    MMA_BF16(c[mi][ni], al[mi], bh[ni]);
                }
        }
        __syncthreads();
        buf ^= 1;
    }
#undef LD_TILE

#pragma unroll
    for (int mi = 0; mi < 2; mi++) {
        int r0 = bm + warp_m + mi*16 + g;
        int r1 = r0 + 8;
#pragma unroll
        for (int ni = 0; ni < 4; ni++) {
            int cb = bn + warp_n + ni*8 + 2*tg;
            float b0 = bias[cb], b1 = bias[cb+1];
            float v0 = fmaxf(c[mi][ni][0] + b0, 0.f);
            float v1 = fmaxf(c[mi][ni][1] + b1, 0.f);
            float v2 = fmaxf(c[mi][ni][2] + b0, 0.f);
            float v3 = fmaxf(c[mi][ni][3] + b1, 0.f);
            unsigned h01, l01, h23, l23;
            split2(v0, v1, h01, l01);
            split2(v2, v3, h23, l23);
            *reinterpret_cast<unsigned*>(&Ch[(size_t)r0*N + cb]) = h01;
            *reinterpret_cast<unsigned*>(&Cl[(size_t)r0*N + cb]) = l01;
            *reinterpret_cast<unsigned*>(&Ch[(size_t)r1*N + cb]) = h23;
            *reinterpret_cast<unsigned*>(&Cl[(size_t)r1*N + cb]) = l23;
        }
    }
}

/* ---------------- skinny GEMM, N=16, fp32 input (u-MLP) -------------------- */
__global__ __launch_bounds__(256,4)
void k_gemm16(const float* __restrict__ X, int lda,
              const float* __restrict__ W, int ldw,
              const float* __restrict__ bias, float* __restrict__ C,
              int M, int K, int relu, float scale)
{
    __shared__ __align__(16) float As[16][BM+4];
    __shared__ float Bs[16][17];
    const int t = threadIdx.x;
    const int bm = blockIdx.x * BM;
    const int arow = t >> 1, acol = (t & 1) << 3;
    const int tx = t & 15, ty = t >> 4;
    const bool xok = (bm + arow) < M;
    const float4 z4 = make_float4(0.f,0.f,0.f,0.f);

    float acc[8];
#pragma unroll
    for (int i = 0; i < 8; i++) acc[i] = 0.f;

    for (int k0 = 0; k0 < K; k0 += 16) {
        float4 v0 = z4, v1 = z4;
        if (xok) {
            v0 = *reinterpret_cast<const float4*>(X + (size_t)(bm+arow)*lda + k0 + acol);
            v1 = *reinterpret_cast<const float4*>(X + (size_t)(bm+arow)*lda + k0 + acol + 4);
        }
        float4 wv = z4;
        int wr = t >> 2, wc = (t & 3) << 2;
        if (t < 64) wv = *reinterpret_cast<const float4*>(W + (size_t)wr*ldw + k0 + wc);
        __syncthreads();
        As[acol+0][arow]=v0.x; As[acol+1][arow]=v0.y; As[acol+2][arow]=v0.z; As[acol+3][arow]=v0.w;
        As[acol+4][arow]=v1.x; As[acol+5][arow]=v1.y; As[acol+6][arow]=v1.z; As[acol+7][arow]=v1.w;
        if (t < 64) { Bs[wc+0][wr]=wv.x; Bs[wc+1][wr]=wv.y; Bs[wc+2][wr]=wv.z; Bs[wc+3][wr]=wv.w; }
        __syncthreads();
#pragma unroll
        for (int k = 0; k < 16; k++) {
            float b = Bs[k][tx];
            float4 a0 = *reinterpret_cast<const float4*>(&As[k][ty*8]);
            float4 a1 = *reinterpret_cast<const float4*>(&As[k][ty*8+4]);
            acc[0]=fmaf(a0.x,b,acc[0]); acc[1]=fmaf(a0.y,b,acc[1]);
            acc[2]=fmaf(a0.z,b,acc[2]); acc[3]=fmaf(a0.w,b,acc[3]);
            acc[4]=fmaf(a1.x,b,acc[4]); acc[5]=fmaf(a1.y,b,acc[5]);
            acc[6]=fmaf(a1.z,b,acc[6]); acc[7]=fmaf(a1.w,b,acc[7]);
        }
        __syncthreads();
    }
    float bb = bias[tx];
#pragma unroll
    for (int i = 0; i < 8; i++) {
        int r = bm + ty*8 + i;
        if (r >= M) continue;
        float v = acc[i] + bb;
        if (relu) v = fmaxf(v, 0.f);
        C[(size_t)r*16 + tx] = v * scale;
    }
}

/* ---------------- fused tail: layer3 (both dirs) + merge + layer4 ---------- */
__global__ __launch_bounds__(256,2)
void k_tail(const __nv_bfloat16* __restrict__ Xh, const __nv_bfloat16* __restrict__ Xl,
            const float* __restrict__ W3, const float* __restrict__ b3,
            const float* __restrict__ W4, const float* __restrict__ b4,
            float* __restrict__ out_p)
{
    __shared__ __align__(16) float As[16][BM+4];
    __shared__ float Bs[16][17];
    __shared__ float Z[128][17];
    const int t = threadIdx.x;
    const int base = blockIdx.x * 128;
    const int arow = t >> 1, acol = (t & 1) << 3;
    const int tx = t & 15, ty = t >> 4;

#pragma unroll
    for (int d = 0; d < 2; d++) {
        float acc[8];
#pragma unroll
        for (int i = 0; i < 8; i++) acc[i] = 0.f;
        const size_t roff = (size_t)(base + arow + d*Ee) * 256;

        for (int k0 = 0; k0 < 256; k0 += 16) {
            uint4 uh = *reinterpret_cast<const uint4*>(Xh + roff + k0 + acol);
            uint4 ul = *reinterpret_cast<const uint4*>(Xl + roff + k0 + acol);
            float4 wv = make_float4(0.f,0.f,0.f,0.f);
            int wr = t >> 2, wc = (t & 3) << 2;
            if (t < 64) wv = *reinterpret_cast<const float4*>(W3 + (size_t)wr*256 + k0 + wc);
            __syncthreads();
            {
                const unsigned* ph = reinterpret_cast<const unsigned*>(&uh);
                const unsigned* pl = reinterpret_cast<const unsigned*>(&ul);
#pragma unroll
                for (int q = 0; q < 4; q++) {
                    __nv_bfloat162 hh = *reinterpret_cast<const __nv_bfloat162*>(&ph[q]);
                    __nv_bfloat162 ll = *reinterpret_cast<const __nv_bfloat162*>(&pl[q]);
                    float2 fh = __bfloat1622float2(hh);
                    float2 fl = __bfloat1622float2(ll);
                    As[acol + 2*q    ][arow] = fh.x + fl.x;
                    As[acol + 2*q + 1][arow] = fh.y + fl.y;
                }
            }
            if (t < 64) { Bs[wc+0][wr]=wv.x; Bs[wc+1][wr]=wv.y; Bs[wc+2][wr]=wv.z; Bs[wc+3][wr]=wv.w; }
            __syncthreads();
#pragma unroll
            for (int k = 0; k < 16; k++) {
                float b = Bs[k][tx];
                float4 a0 = *reinterpret_cast<const float4*>(&As[k][ty*8]);
                float4 a1 = *reinterpret_cast<const float4*>(&As[k][ty*8+4]);
                acc[0]=fmaf(a0.x,b,acc[0]); acc[1]=fmaf(a0.y,b,acc[1]);
                acc[2]=fmaf(a0.z,b,acc[2]); acc[3]=fmaf(a0.w,b,acc[3]);
                acc[4]=fmaf(a1.x,b,acc[4]); acc[5]=fmaf(a1.y,b,acc[5]);
                acc[6]=fmaf(a1.z,b,acc[6]); acc[7]=fmaf(a1.w,b,acc[7]);
            }
        }
        float bb = b3[tx];
#pragma unroll
        for (int i = 0; i < 8; i++) {
            float v = fmaxf(acc[i] + bb, 0.f);
            if (d == 0) Z[ty*8 + i][tx] = v;
            else        Z[ty*8 + i][tx] += v;
        }
        __syncthreads();
    }

    float w4r[16];
#pragma unroll
    for (int k = 0; k < 16; k++) w4r[k] = W4[t*16 + k];
    const float bb4 = 2.f * b4[t];
    const float sc = 0.5f / (float)Ee;
    for (int r = 0; r < 128; r++) {
        float s = bb4;
#pragma unroll
        for (int k = 0; k < 16; k++) s = fmaf(Z[r][k], w4r[k], s);
        out_p[(size_t)(base + r)*256 + t] = s * sc;
    }
}

/* ---------------- GRU elementwise ------------------------------------------ */
__global__ void k_gru(const float* __restrict__ hprev, float* __restrict__ out_h) {
    int idx = blockIdx.x*blockDim.x + threadIdx.x;
    if (idx >= Nn*Hh) return;
    int n = idx / Hh, d = idx % Hh;
    const float* gi = g_gi + n*G3;
    const float* gh = g_gh + n*G3;
    float r = 1.f/(1.f + expf(-(gi[d]       + gh[d])));
    float z = 1.f/(1.f + expf(-(gi[Hh+d]    + gh[Hh+d])));
    float t = tanhf(gi[2*Hh+d] + r*gh[2*Hh+d]);
    float h = (1.f - z)*t + z*hprev[idx];
    g_h[idx] = h;
    out_h[idx] = h;
}

/* ---------------- p-layer0 (row-range chunk): relu(hA+hB+b0) -> split bf16 - */
__global__ void k_edge0(const int* __restrict__ edges, const float* __restrict__ b0,
                        int ro, int cnt) {
    int idx = blockIdx.x*blockDim.x + threadIdx.x;
    if (idx >= cnt*32) return;
    int r = ro + (idx >> 5);
    int c = (idx & 31) << 2;
    int e = (r < Ee) ? r : r - Ee;
    int i = edges[2*e], j = edges[2*e+1];
    int na = (r < Ee) ? i : j;
    int nb = (r < Ee) ? j : i;
    float4 a = *reinterpret_cast<const float4*>(&g_hA[na*Hh + c]);
    float4 b = *reinterpret_cast<const float4*>(&g_hB[nb*Hh + c]);
    float4 bb = *reinterpret_cast<const float4*>(&b0[c]);
    float v0 = fmaxf(a.x + b.x + bb.x, 0.f);
    float v1 = fmaxf(a.y + b.y + bb.y, 0.f);
    float v2 = fmaxf(a.z + b.z + bb.z, 0.f);
    float v3 = fmaxf(a.w + b.w + bb.w, 0.f);
    unsigned h01, l01, h23, l23;
    split2(v0, v1, h01, l01);
    split2(v2, v3, h23, l23);
    size_t base = (size_t)r*Hh + c;
    *reinterpret_cast<unsigned*>(&g_a0h[base])     = h01;
    *reinterpret_cast<unsigned*>(&g_a0h[base + 2]) = h23;
    *reinterpret_cast<unsigned*>(&g_a0l[base])     = l01;
    *reinterpret_cast<unsigned*>(&g_a0l[base + 2]) = l23;
}

/* ---------------- message update, 2 edges/warp + fused scatter ------------- */
__global__ void k_msg(const int* __restrict__ edges, const float* __restrict__ u,
                      const float* __restrict__ p, int cur, int nxt) {
    int gt = blockIdx.x*blockDim.x + threadIdx.x;
    int w = gt >> 4;
    if (w >= Ee) return;
    if (!g_isrep[w]) return;
    const unsigned gmask = 0xffffu << (threadIdx.x & 16);
    int b = threadIdx.x & 15;
    const float* S  = g_S + cur*Nn*Aa;
    float*       Sn = g_S + nxt*Nn*Aa;
    int i = edges[2*w], j = edges[2*w+1];
    float Mi = g_M[(w*2 + 0)*Aa + b];
    float Mj = g_M[(w*2 + 1)*Aa + b];
    float base_i = u[i*Aa + b] + S[i*Aa + b] - Mi;
    float base_j = u[j*Aa + b] + S[j*Aa + b] - Mj;
    const float* pe = p + (size_t)w*256;
    float mtj = -FLT_MAX, colmax = -FLT_MAX;
#pragma unroll
    for (int a2 = 0; a2 < 16; a2++) {
        float pab = pe[a2*16 + b];
        float bia = __shfl_sync(gmask, base_i, a2, 16);
        mtj    = fmaxf(mtj, pab + bia);
        colmax = fmaxf(colmax, pab);
    }
    float mti = colmax + base_j;
    float s1 = mtj, s2 = mti;
#pragma unroll
    for (int m = 8; m; m >>= 1) {
        s1 += __shfl_xor_sync(gmask, s1, m, 16);
        s2 += __shfl_xor_sync(gmask, s2, m, 16);
    }
    mtj -= s1 * (1.f/16.f);
    mti -= s2 * (1.f/16.f);
    g_M[(w*2 + 1)*Aa + b] = mtj;
    g_M[(w*2 + 0)*Aa + b] = mti;
    atomicAdd(&Sn[i*Aa + b], mti);
    atomicAdd(&Sn[j*Aa + b], mtj);
}

/* ---------------- per-node argmax (aidx only) ------------------------------- */
__global__ void k_argmax(const float* __restrict__ u, int sb, int ab) {
    int idx = blockIdx.x*blockDim.x + threadIdx.x;
    if (idx >= Nn) return;
    const float* S = g_S + sb*Nn*Aa;
    float best = -FLT_MAX; int bi = 0;
#pragma unroll
    for (int a = 0; a < Aa; a++) {
        float v = u[idx*Aa + a] + S[idx*Aa + a];
        if (v > best) { best = v; bi = a; }
    }
    g_aidx[ab][idx] = bi;
}

/* ---------------- zero one S buffer ----------------------------------------- */
__global__ void k_zero(int sb) {
    int idx = blockIdx.x*blockDim.x + threadIdx.x;
    if (idx < Nn*Aa) g_S[sb*Nn*Aa + idx] = 0.f;
}

/* ---------------- q partial sums + fused last-block final reduce ----------- */
__global__ void k_qstep(const int* __restrict__ edges, const float* __restrict__ u,
                        const float* __restrict__ p, int ab) {
    __shared__ float red[256];
    __shared__ int lastdone;
    const int* aidx = g_aidx[ab];
    int tid = threadIdx.x, bid = blockIdx.x;
    int gt = bid*256 + tid;
    float local = 0.f;
    for (int n = gt; n < Nn; n += 64*256) local += u[n*Aa + aidx[n]];
    for (int e = gt; e < Ee; e += 64*256) {
        int i = edges[2*e], j = edges[2*e+1];
        local += p[(size_t)e*256 + aidx[i]*Aa + aidx[j]];
    }
    red[tid] = local;
    __syncthreads();
    for (int s = 128; s > 0; s >>= 1) {
        if (tid < s) red[tid] += red[tid + s];
        __syncthreads();
    }
    if (tid == 0) {
        g_part[bid] = red[0];
        __threadfence();
        int done = atomicAdd(&g_qctr, 1);
        lastdone = (done == 63) ? 1 : 0;
    }
    __syncthreads();
    if (!lastdone) return;
    __shared__ int better;
    if (tid == 0) {
        float q = 0.f;
        for (int k = 0; k < 64; k++) q += g_part[k];
        if (q > g_qmax) { g_qmax = q; better = 1; } else better = 0;
        g_qctr = 0;
    }
    __syncthreads();
    if (better) {
        for (int n = tid; n < Nn; n += 256) g_best[n] = g_aidx[ab][n];
    }
}

/* ---------------- finalize --------------------------------------------------- */
__global__ void k_final(float* __restrict__ out) {
    int idx = blockIdx.x*blockDim.x + threadIdx.x;
    if (idx >= Nn*Aa) return;
    int n = idx >> 4, a = idx & 15;
    out[idx] = (g_best[n] == a) ? 1.f : 0.f;
    if (idx == 0) out[Nn*Aa] = g_qmax;
}

/* ---------------- host ------------------------------------------------------- */
static inline void gemm(cudaStream_t st, const float* X, int lda, const float* W, int ldw,
                        const float* b, float* C, int M, int N, int K,
                        int relu, float scale, float bias_mult, int vec_store) {
    dim3 grid(N/BN, (M + BM - 1)/BM);
    k_gemm128<<<grid, 256, 0, st>>>(X, lda, W, ldw, b, C, M, N, K, relu, scale, bias_mult, vec_store);
}

extern "C" void kernel_launch(void* const* d_in, const int* in_sizes, int n_in,
                              void* d_out, int out_size) {
    const float* x    = (const float*)d_in[0];
    const float* pa   = (const float*)d_in[1];
    const float* st   = (const float*)d_in[2];
    const int*   edges= (const int*)  d_in[3];
    const float* wih  = (const float*)d_in[4];
    const float* whh  = (const float*)d_in[5];
    const float* bih  = (const float*)d_in[6];
    const float* bhh  = (const float*)d_in[7];
    const float* uW0  = (const float*)d_in[8];   const float* ub0 = (const float*)d_in[9];
    const float* uW1  = (const float*)d_in[10];  const float* ub1 = (const float*)d_in[11];
    const float* uW2  = (const float*)d_in[12];  const float* ub2 = (const float*)d_in[13];
    const float* pW0  = (const float*)d_in[14];  const float* pb0 = (const float*)d_in[15];
    const float* pW1  = (const float*)d_in[16];  const float* pb1 = (const float*)d_in[17];
    const float* pW2  = (const float*)d_in[18];  const float* pb2 = (const float*)d_in[19];
    const float* pW3  = (const float*)d_in[20];  const float* pb3 = (const float*)d_in[21];
    const float* pW4  = (const float*)d_in[22];  const float* pb4 = (const float*)d_in[23];

    float* out   = (float*)d_out;
    float* out_u = out + Nn*Aa + 1;
    float* out_p = out_u + Nn*Aa;
    float* out_h = out_p + (size_t)Ee*Aa*Aa;

    float *gi_, *gh_, *h_, *hA_, *hB_, *ua_, *ub_;
    __nv_bfloat16 *a0h_, *a0l_, *a1h_, *a1l_, *a2h_, *a2l_, *w1h_, *w1l_, *w2h_, *w2l_;
    cudaGetSymbolAddress((void**)&gi_,   g_gi);
    cudaGetSymbolAddress((void**)&gh_,   g_gh);
    cudaGetSymbolAddress((void**)&h_,    g_h);
    cudaGetSymbolAddress((void**)&hA_,   g_hA);
    cudaGetSymbolAddress((void**)&hB_,   g_hB);
    cudaGetSymbolAddress((void**)&ua_,   g_ua);
    cudaGetSymbolAddress((void**)&ub_,   g_ub);
    cudaGetSymbolAddress((void**)&a0h_,  g_a0h);
    cudaGetSymbolAddress((void**)&a0l_,  g_a0l);
    cudaGetSymbolAddress((void**)&a1h_,  g_a1h);
    cudaGetSymbolAddress((void**)&a1l_,  g_a1l);
    cudaGetSymbolAddress((void**)&a2h_,  g_a2h);
    cudaGetSymbolAddress((void**)&a2l_,  g_a2l);
    cudaGetSymbolAddress((void**)&w1h_,  g_w1h);
    cudaGetSymbolAddress((void**)&w1l_,  g_w1l);
    cudaGetSymbolAddress((void**)&w2h_,  g_w2h);
    cudaGetSymbolAddress((void**)&w2l_,  g_w2l);

    static cudaStream_t s1 = 0, s2 = 0, s3 = 0;
    static cudaEvent_t e0 = 0, e_gh, e_gru, e_u, e_hb, e_ha, e_s1, e_w, e_d1;
    static cudaEvent_t evM[NITER], evZ[NITER], evA[NITER], evQ[NITER];
    if (!e0) {
        cudaStreamCreateWithFlags(&s1, cudaStreamNonBlocking);
        cudaStreamCreateWithFlags(&s2, cudaStreamNonBlocking);
        cudaStreamCreateWithFlags(&s3, cudaStreamNonBlocking);
        cudaEventCreateWithFlags(&e0,   cudaEventDisableTiming);
        cudaEventCreateWithFlags(&e_gh, cudaEventDisableTiming);
        cudaEventCreateWithFlags(&e_gru,cudaEventDisableTiming);
        cudaEventCreateWithFlags(&e_u,  cudaEventDisableTiming);
        cudaEventCreateWithFlags(&e_hb, cudaEventDisableTiming);
        cudaEventCreateWithFlags(&e_ha, cudaEventDisableTiming);
        cudaEventCreateWithFlags(&e_s1, cudaEventDisableTiming);
        cudaEventCreateWithFlags(&e_w,  cudaEventDisableTiming);
        cudaEventCreateWithFlags(&e_d1, cudaEventDisableTiming);
        for (int t = 0; t < NITER; t++) {
            cudaEventCreateWithFlags(&evM[t], cudaEventDisableTiming);
            cudaEventCreateWithFlags(&evZ[t], cudaEventDisableTiming);
            cudaEventCreateWithFlags(&evA[t], cudaEventDisableTiming);
            cudaEventCreateWithFlags(&evQ[t], cudaEventDisableTiming);
        }
    }

    /* fork */
    cudaEventRecord(e0, 0);
    cudaStreamWaitEvent(s1, e0, 0);
    cudaStreamWaitEvent(s2, e0, 0);
    cudaStreamWaitEvent(s3, e0, 0);

    /* s1: MP state init + duplicate-edge dedup */
    k_init<<<1024, 256, 0, s1>>>();
    k_clearmap<<<(Ee + 255)/256, 256, 0, s1>>>(edges);
    k_mapbuild<<<(Ee + 255)/256, 256, 0, s1>>>(edges);
    k_isrep<<<(Ee + 255)/256, 256, 0, s1>>>(edges);
    cudaEventRecord(e_s1, s1);

    /* s3: weight splits */
    k_wsplit<<<(256*Hh + 255)/256, 256, 0, s3>>>(pW1, 256*Hh, w1h_, w1l_);
    k_wsplit<<<(256*256 + 255)/256, 256, 0, s3>>>(pW2, 256*256, w2h_, w2l_);
    cudaEventRecord(e_w, s3);

    /* s2: gh GEMM */
    gemm(s2, st, Hh, whh, Hh, bhh, gh_, Nn, G3, Hh, 0, 1.f, 1.f, 1);
    cudaEventRecord(e_gh, s2);

    /* 0: gi GEMM with fused concat, then GRU */
    {
        dim3 grid(G3/BN, (Nn + BM - 1)/BM);
        k_gemmGI<<<grid, 256>>>(x, pa, wih, IN_DIM, bih, gi_, Nn, G3, IN_DIM);
    }
    cudaStreamWaitEvent(0, e_gh, 0);
    k_gru<<<(Nn*Hh + 255)/256, 256>>>(st, out_h);
    cudaEventRecord(e_gru, 0);

    /* s2: utility MLP */
    cudaStreamWaitEvent(s2, e_gru, 0);
    gemm(s2, h_,  Hh,  uW0, Hh,  ub0, ua_, Nn, 256, Hh,  1, 1.f, 1.f, 1);
    gemm(s2, ua_, 256, uW1, 256, ub1, ub_, Nn, 256, 256, 1, 1.f, 1.f, 1);
    k_gemm16<<<(Nn + BM - 1)/BM, 256, 0, s2>>>(ub_, 256, uW2, 256, ub2, out_u, Nn, 256, 0, 1.f/(float)Nn);
    cudaEventRecord(e_u, s2);

    /* s3: hB GEMM */
    cudaStreamWaitEvent(s3, e_gru, 0);
    gemm(s3, h_, Hh, pW0 + Hh, 2*Hh, pb0, hB_, Nn, Hh, Hh, 0, 1.f, 0.f, 1);
    cudaEventRecord(e_hb, s3);

    /* 0: hA GEMM */
    gemm(0, h_, Hh, pW0, 2*Hh, pb0, hA_, Nn, Hh, Hh, 0, 1.f, 0.f, 1);
    cudaEventRecord(e_ha, 0);

    /* direction-split p-chain: d0 on stream 0, d1 on s3 (both halves run
       concurrently, filling each other's tail waves) */
    {
        dim3 gh1(256/TBN, Ee/TBM);   /* half-grid: 125 M-tiles */
        /* stream 0: d0 rows [0, Ee) */
        cudaStreamWaitEvent(0, e_hb, 0);
        cudaStreamWaitEvent(0, e_w, 0);
        k_edge0<<<(Ee*32 + 255)/256, 256>>>(edges, pb0, 0, Ee);
        k_tgemm<<<gh1, 256>>>(a0h_, a0l_, w1h_, w1l_, pb1, Ee, 256, Hh,  a1h_, a1l_);
        k_tgemm<<<gh1, 256>>>(a1h_, a1l_, w2h_, w2l_, pb2, Ee, 256, 256, a2h_, a2l_);
        /* s3: d1 rows [Ee, 2Ee) (hB already local; needs hA + weights) */
        cudaStreamWaitEvent(s3, e_ha, 0);
        k_edge0<<<(Ee*32 + 255)/256, 256, 0, s3>>>(edges, pb0, Ee, Ee);
        k_tgemm<<<gh1, 256, 0, s3>>>(a0h_ + (size_t)Ee*Hh,  a0l_ + (size_t)Ee*Hh,  w1h_, w1l_, pb1, Ee, 256, Hh,  a1h_ + (size_t)Ee*256, a1l_ + (size_t)Ee*256);
        k_tgemm<<<gh1, 256, 0, s3>>>(a1h_ + (size_t)Ee*256, a1l_ + (size_t)Ee*256, w2h_, w2l_, pb2, Ee, 256, 256, a2h_ + (size_t)Ee*256, a2l_ + (size_t)Ee*256);
        cudaEventRecord(e_d1, s3);
    }
    cudaStreamWaitEvent(0, e_d1, 0);
    k_tail<<<Ee/128, 256>>>(a2h_, a2l_, pW3, pb3, pW4, pb4, out_p);

    /* join: msg needs u, p, isrep, S zeroed */
    cudaStreamWaitEvent(0, e_u, 0);
    cudaStreamWaitEvent(0, e_s1, 0);

    /* MP: msg-only critical path on stream 0.
       s2: argmax (fast) + zero recycled S buffer.
       s3: qstep (heavy, deterministic reduce), off critical path.
       (s3 is in-order past its front work; qstep(0) additionally waits evA[0].) */
    for (int t = 0; t < NITER; t++) {
        int cur = t % 3, nxt = (t + 1) % 3, ab = t & 1;
        if (t >= 2) cudaStreamWaitEvent(0, evZ[t-2], 0);
        k_msg<<<(Ee*16 + 255)/256, 256>>>(edges, out_u, out_p, cur, nxt);
        cudaEventRecord(evM[t], 0);
        cudaStreamWaitEvent(s2, evM[t], 0);
        if (t >= 2) cudaStreamWaitEvent(s2, evQ[t-2], 0);  /* aidx[ab] reuse */
        k_argmax<<<(Nn + 255)/256, 256, 0, s2>>>(out_u, nxt, ab);
        cudaEventRecord(evA[t], s2);
        k_zero<<<(Nn*Aa + 255)/256, 256, 0, s2>>>(cur);
        cudaEventRecord(evZ[t], s2);
        cudaStreamWaitEvent(s3, evA[t], 0);
        k_qstep<<<64, 256, 0, s3>>>(edges, out_u, out_p, ab);
        cudaEventRecord(evQ[t], s3);
    }
    /* join ALL side streams back into the capture stream */
    cudaStreamWaitEvent(0, evQ[NITER-1], 0);   /* s3 tail */
    cudaStreamWaitEvent(0, evZ[NITER-1], 0);   /* s2 tail (covers argmax+zero) */

    k_final<<<(Nn*Aa + 255)/256, 256>>>(out);
}